// round 3
// baseline (speedup 1.0000x reference)
#include <cuda_runtime.h>

// ---------------------------------------------------------------------------
// G2Conv2d4: per-quadrant energy argmax -> one-hot guided rect-cummax pool
//            -> 3x3 SAME conv.
// Guide is one-hot => guided pool collapses to
//   pooled[c,i,j] = in-rect(i,j) ? max(x^2, x^2[landmark]) : x^2
// Round 3: packed fma.rn.f32x2 inner loop (2 FMA/slot), pooled tensor
// precomputed to __device__ scratch, duplicated-float2 smem staging so no
// pack MOVs are needed, CK=8, conflict-free smem strides.
// ---------------------------------------------------------------------------

__device__ unsigned long long g_key[64];                  // (energyBits<<32)|~p
__device__ float g_pooled[16u * 256u * 64u * 64u];        // 64 MB scratch

// ---------------- packed f32x2 helpers ----------------
__device__ __forceinline__ void ffma2(unsigned long long& d,
                                      unsigned long long a,
                                      unsigned long long b) {
    asm("fma.rn.f32x2 %0, %1, %2, %0;" : "+l"(d) : "l"(a), "l"(b));
}
__device__ __forceinline__ float2 u2f2(unsigned long long v) {
    float2 r;
    asm("mov.b64 {%0, %1}, %2;" : "=f"(r.x), "=f"(r.y) : "l"(v));
    return r;
}

// ---------------- Kernel 0: reset argmax keys ----------------
__global__ void init_keys_kernel() {
    if (threadIdx.x < 64) g_key[threadIdx.x] = 0ull;
}

// ---------------- Kernel 1: per-(b,q) energy argmax (512 blocks) ----------
// key = (float_bits(energy) << 32) | (u32)~p ; energy >= 0 so bits are
// monotonic; max key => max energy, ties broken toward smallest p.
__global__ void energy_argmax_kernel(const float* __restrict__ x) {
    int bq    = blockIdx.x >> 3;          // 0..63
    int slice = blockIdx.x & 7;           // 512 pixels per slice
    int b = bq >> 2, q = bq & 3;
    const float* xb = x + (((size_t)b * 256 + q * 64) << 12);

    unsigned long long best = 0ull;
    int p0 = slice * 512;
    for (int p = p0 + threadIdx.x; p < p0 + 512; p += 256) {
        float s = 0.0f;
#pragma unroll 8
        for (int c = 0; c < 64; ++c) {
            float v = xb[((size_t)c << 12) + p];
            s = fmaf(v, v, s);
        }
        unsigned long long key =
            ((unsigned long long)__float_as_uint(s) << 32) |
            (unsigned long long)(unsigned)(~p);
        if (key > best) best = key;
    }

    __shared__ unsigned long long sk[256];
    sk[threadIdx.x] = best;
    __syncthreads();
    for (int off = 128; off; off >>= 1) {
        if (threadIdx.x < off) {
            unsigned long long o = sk[threadIdx.x + off];
            if (o > sk[threadIdx.x]) sk[threadIdx.x] = o;
        }
        __syncthreads();
    }
    if (threadIdx.x == 0) atomicMax(&g_key[bq], sk[0]);
}

// ---------------- Kernel 2: materialize pooled tensor ----------------
__global__ void pool_kernel(const float* __restrict__ x) {
    int blk = blockIdx.x;                 // b*256 + c
    int b = blk >> 8, c = blk & 255, q = c >> 6;

    unsigned long long key = g_key[(b << 2) | q];
    int p = (int)(~(unsigned)key) & 4095;
    int r = p >> 6, cc = p & 63;

    const float* xp = x + ((size_t)blk << 12);
    float* op = g_pooled + ((size_t)blk << 12);

    float lv = xp[(r << 6) | cc];
    lv *= lv;
    bool topH  = (q < 2);
    bool leftW = ((q & 1) == 0);

    for (int i = threadIdx.x; i < 1024; i += 256) {   // float4 granularity
        float4 v = ((const float4*)xp)[i];
        int pix = i << 2;
        int y = pix >> 6, x0 = pix & 63;
        bool ch = topH ? (y <= r) : (y >= r);
        float4 o;
        o.x = v.x * v.x; o.y = v.y * v.y; o.z = v.z * v.z; o.w = v.w * v.w;
        if (ch) {
            if (leftW ? (x0     <= cc) : (x0     >= cc)) o.x = fmaxf(o.x, lv);
            if (leftW ? (x0 + 1 <= cc) : (x0 + 1 >= cc)) o.y = fmaxf(o.y, lv);
            if (leftW ? (x0 + 2 <= cc) : (x0 + 2 >= cc)) o.z = fmaxf(o.z, lv);
            if (leftW ? (x0 + 3 <= cc) : (x0 + 3 >= cc)) o.w = fmaxf(o.w, lv);
        }
        ((float4*)op)[i] = o;
    }
}

// ---------------- Kernel 3: 3x3 conv, packed f32x2 core ----------------
// Block: 64 co x 16x16 spatial tile, one batch. 256 threads.
// Per-thread: 4 co-pairs x 8 px accumulators (fma.rn.f32x2).
#define CK 8

__global__ __launch_bounds__(256, 2)
void conv_kernel(const float* __restrict__ w,
                 const float* __restrict__ bias,
                 float* __restrict__ out) {
    // input tile stored DUPLICATED: in_s[..] = (v, v). Row stride 22 float2
    // (176B) keeps the LDS.128 pattern phase-conflict-free.
    __shared__ float2 in_s[CK][18][22];
    __shared__ float  w_s[CK][9][64];

    const int tid = threadIdx.x;
    const int b = blockIdx.z;
    const int co_base = blockIdx.y * 64;
    const int s = blockIdx.x;
    const int ty0 = (s >> 2) << 4;
    const int tx0 = (s & 3) << 4;

    const float* pb = g_pooled + ((size_t)b << 20);

    const int tco  = tid >> 5;            // 0..7, uniform per warp
    const int lane = tid & 31;
    const int py   = lane >> 1;           // 0..15
    const int px0  = (lane & 1) << 3;     // 0 or 8

    unsigned long long acc[4][8];         // (0.f,0.f) bits == 0
#pragma unroll
    for (int kp = 0; kp < 4; ++kp)
#pragma unroll
        for (int j = 0; j < 8; ++j) acc[kp][j] = 0ull;

    const int co_l  = tid & 63;
    const int cpart = tid >> 6;           // 0..3

    for (int ci0 = 0; ci0 < 256; ci0 += CK) {
        // ---- weights: w_s[ci_l][tap][co] ----
#pragma unroll
        for (int cc = cpart; cc < CK; cc += 4) {
            const float* wp = w + ((size_t)(co_base + co_l) * 256 + ci0 + cc) * 9;
#pragma unroll
            for (int t = 0; t < 9; ++t)
                w_s[cc][t][co_l] = wp[t];
        }
        // ---- input patch (pool already applied), duplicated float2 ----
        for (int idx = tid; idx < CK * 324; idx += 256) {
            int ci_l = idx / 324;
            int rem  = idx - ci_l * 324;
            int i    = rem / 18;
            int j    = rem - i * 18;
            int y    = ty0 + i - 1;
            int xx   = tx0 + j - 1;
            float p = 0.0f;
            if ((unsigned)y < 64u && (unsigned)xx < 64u)
                p = pb[((size_t)(ci0 + ci_l) << 12) + (y << 6) + xx];
            in_s[ci_l][i][j] = make_float2(p, p);
        }
        __syncthreads();

        // ---- compute ----
#pragma unroll 1
        for (int ci_l = 0; ci_l < CK; ++ci_l) {
#pragma unroll
            for (int dy = 0; dy < 3; ++dy) {
                // 10 duplicated input pairs (cols px0 .. px0+9): 5x LDS.128
                const ulonglong2* rp =
                    (const ulonglong2*)&in_s[ci_l][py + dy][px0];
                ulonglong2 q0 = rp[0], q1 = rp[1], q2 = rp[2],
                           q3 = rp[3], q4 = rp[4];
                unsigned long long wp_[10] = {q0.x, q0.y, q1.x, q1.y, q2.x,
                                              q2.y, q3.x, q3.y, q4.x, q4.y};
#pragma unroll
                for (int dx = 0; dx < 3; ++dx) {
                    // 8 consecutive co weights = 4 pairs: 2x LDS.128 (broadcast)
                    const ulonglong2* wr =
                        (const ulonglong2*)&w_s[ci_l][dy * 3 + dx][tco * 8];
                    ulonglong2 wA = wr[0], wB = wr[1];
                    unsigned long long wpair[4] = {wA.x, wA.y, wB.x, wB.y};
#pragma unroll
                    for (int kp = 0; kp < 4; ++kp)
#pragma unroll
                        for (int j = 0; j < 8; ++j)
                            ffma2(acc[kp][j], wp_[dx + j], wpair[kp]);
                }
            }
        }
        __syncthreads();
    }

    // ---- epilogue: unpack, add bias, vectorized stores ----
#pragma unroll
    for (int kp = 0; kp < 4; ++kp) {
        int co0 = co_base + tco * 8 + 2 * kp;
        float b0 = bias[co0], b1 = bias[co0 + 1];
        float* o0 = out + (((size_t)b * 256 + co0) << 12)
                        + ((ty0 + py) << 6) + tx0 + px0;
        float* o1 = o0 + 4096;

        float2 v0 = u2f2(acc[kp][0]), v1 = u2f2(acc[kp][1]),
               v2 = u2f2(acc[kp][2]), v3 = u2f2(acc[kp][3]),
               v4 = u2f2(acc[kp][4]), v5 = u2f2(acc[kp][5]),
               v6 = u2f2(acc[kp][6]), v7 = u2f2(acc[kp][7]);

        ((float4*)o0)[0] = make_float4(v0.x + b0, v1.x + b0, v2.x + b0, v3.x + b0);
        ((float4*)o0)[1] = make_float4(v4.x + b0, v5.x + b0, v6.x + b0, v7.x + b0);
        ((float4*)o1)[0] = make_float4(v0.y + b1, v1.y + b1, v2.y + b1, v3.y + b1);
        ((float4*)o1)[1] = make_float4(v4.y + b1, v5.y + b1, v6.y + b1, v7.y + b1);
    }
}

// ---------------- launch ----------------
extern "C" void kernel_launch(void* const* d_in, const int* in_sizes, int n_in,
                              void* d_out, int out_size) {
    const float* x    = (const float*)d_in[0];
    const float* w    = (const float*)d_in[1];
    const float* bias = (const float*)d_in[2];
    float* out = (float*)d_out;

    init_keys_kernel<<<1, 64>>>();
    energy_argmax_kernel<<<512, 256>>>(x);
    pool_kernel<<<4096, 256>>>(x);

    dim3 grid(16, 4, 16);   // spatial tiles, co tiles, batch
    conv_kernel<<<grid, 256>>>(w, bias, out);
}

// round 6
// speedup vs baseline: 5.3051x; 5.3051x over previous
#include <cuda_runtime.h>
#include <cuda_bf16.h>
#include <cstdint>

// ---------------------------------------------------------------------------
// G2Conv2d4 via warp-level mma.sync (bf16, base PTX ISA — the bench target is
// sm_103 WITHOUT the 'a' suffix, so tcgen05 is unavailable).
//   argmax -> pooled = in-rect ? max(x^2, landmark) : x^2  (one-hot collapse)
//   conv3x3 = 9 shifted GEMMs; bf16 3-term split (xh*wh + xl*wh + xh*wl).
// CTA: 128 co x 128 px (2 image rows). Warp tile 32co x 64px. ci chunks of 32
// staged in smem with 80B row stride (ldmatrix conflict-free). dx shift via a
// 66-slot px axis with permanent zero border slots (SAME padding for free).
// ---------------------------------------------------------------------------

__device__ unsigned long long g_key[64];
__device__ __align__(16) __nv_bfloat16 g_pth[16ull * 64 * 64 * 256]; // 32MB
__device__ __align__(16) __nv_bfloat16 g_ptl[16ull * 64 * 64 * 256]; // 32MB
__device__ __align__(16) __nv_bfloat16 g_wh[9 * 256 * 256];
__device__ __align__(16) __nv_bfloat16 g_wl[9 * 256 * 256];

__device__ __forceinline__ uint32_t smem_u32(const void* p) {
    uint32_t a;
    asm("{ .reg .u64 t; cvta.to.shared.u64 t, %1; cvt.u32.u64 %0, t; }"
        : "=r"(a) : "l"(p));
    return a;
}

#define LDSM4(r, addr)                                                        \
    asm volatile("ldmatrix.sync.aligned.m8n8.x4.shared.b16 {%0,%1,%2,%3}, [%4];" \
                 : "=r"((r)[0]), "=r"((r)[1]), "=r"((r)[2]), "=r"((r)[3])     \
                 : "r"(addr))

#define MMA16816(d, a, b0, b1)                                                \
    asm volatile(                                                             \
        "mma.sync.aligned.m16n8k16.row.col.f32.bf16.bf16.f32 "                \
        "{%0,%1,%2,%3}, {%4,%5,%6,%7}, {%8,%9}, {%0,%1,%2,%3};"               \
        : "+f"((d)[0]), "+f"((d)[1]), "+f"((d)[2]), "+f"((d)[3])              \
        : "r"((a)[0]), "r"((a)[1]), "r"((a)[2]), "r"((a)[3]), "r"(b0), "r"(b1))

// ---------------- Kernel 0: reset argmax keys ----------------
__global__ void init_keys_kernel() {
    if (threadIdx.x < 64) g_key[threadIdx.x] = 0ull;
}

// ---------------- Kernel 1: per-(b,q) energy argmax ----------------
__global__ void energy_argmax_kernel(const float* __restrict__ x) {
    int bq    = blockIdx.x >> 3;
    int slice = blockIdx.x & 7;
    int b = bq >> 2, q = bq & 3;
    const float* xb = x + (((size_t)b * 256 + q * 64) << 12);

    unsigned long long best = 0ull;
    int p0 = slice * 512;
    for (int p = p0 + threadIdx.x; p < p0 + 512; p += 256) {
        float s = 0.0f;
#pragma unroll 8
        for (int c = 0; c < 64; ++c) {
            float v = xb[((size_t)c << 12) + p];
            s = fmaf(v, v, s);
        }
        unsigned long long key =
            ((unsigned long long)__float_as_uint(s) << 32) |
            (unsigned long long)(unsigned)(~p);
        if (key > best) best = key;
    }
    __shared__ unsigned long long sk[256];
    sk[threadIdx.x] = best;
    __syncthreads();
    for (int off = 128; off; off >>= 1) {
        if (threadIdx.x < off) {
            unsigned long long o = sk[threadIdx.x + off];
            if (o > sk[threadIdx.x]) sk[threadIdx.x] = o;
        }
        __syncthreads();
    }
    if (threadIdx.x == 0) atomicMax(&g_key[bq], sk[0]);
}

// ---------------- Kernel 2: pooled x^2 -> bf16 hi/lo, px-major ----------
// layout: [((b*64+y)*64 + px) * 256 + ci]
__global__ void pool_split_kernel(const float* __restrict__ x) {
    int bid = blockIdx.x;              // b*64 + y
    int b = bid >> 6, y = bid & 63;
    int ci = threadIdx.x;
    int q = ci >> 6;

    unsigned long long key = g_key[(b << 2) | q];
    int p = (int)(~(unsigned)key) & 4095;
    int r = p >> 6, c = p & 63;

    const float* xc = x + ((size_t)(b * 256 + ci) << 12);
    float lv = xc[(r << 6) | c];
    lv *= lv;
    bool ch = (q < 2) ? (y <= r) : (y >= r);
    bool leftW = ((q & 1) == 0);

    const float4* row4 = (const float4*)(xc + (y << 6));
    size_t obase = (((size_t)bid << 6) << 8) + ci;

#pragma unroll 4
    for (int i = 0; i < 16; ++i) {
        float4 v = row4[i];
        int x0 = i << 2;
        float s[4] = {v.x * v.x, v.y * v.y, v.z * v.z, v.w * v.w};
        if (ch) {
#pragma unroll
            for (int j = 0; j < 4; ++j)
                if (leftW ? (x0 + j <= c) : (x0 + j >= c)) s[j] = fmaxf(s[j], lv);
        }
#pragma unroll
        for (int j = 0; j < 4; ++j) {
            __nv_bfloat16 h = __float2bfloat16(s[j]);
            __nv_bfloat16 l = __float2bfloat16(s[j] - __bfloat162float(h));
            size_t o = obase + ((size_t)(x0 + j) << 8);
            g_pth[o] = h;
            g_ptl[o] = l;
        }
    }
}

// ---------------- Kernel 3: weight bf16 hi/lo split ----------------
// layout: [(tap*256 + co) * 256 + ci]
__global__ void wsplit_kernel(const float* __restrict__ w) {
    int e = blockIdx.x * 256 + threadIdx.x;
    float v = w[e];
    int tap = e % 9;
    int t2 = e / 9;
    int ci = t2 & 255, co = t2 >> 8;
    __nv_bfloat16 h = __float2bfloat16(v);
    __nv_bfloat16 l = __float2bfloat16(v - __bfloat162float(h));
    int o = (tap * 256 + co) * 256 + ci;
    g_wh[o] = h;
    g_wl[o] = l;
}

// ---------------- Kernel 4: mma.sync conv ----------------
// smem: xs[term(2)][row(4)][slot(66)][32ci bf16] stride 80B; then
//       ws[buf(2)][term(2)][co(128)][32ci] stride 80B.
#define XS_M 5280            // 66*80
#define XS_T 21120           // 4*XS_M
#define OFF_WS 42240         // 2*XS_T
#define WS_T 10240           // 128*80
#define WS_B 20480           // 2*WS_T
#define SMEM_TOTAL (OFF_WS + 2 * WS_B)   // 83200

__global__ __launch_bounds__(256, 2)
void conv_mma_kernel(const float* __restrict__ bias, float* __restrict__ out) {
    extern __shared__ __align__(16) char smem[];
    const uint32_t sb = smem_u32(smem);
    const int tid = threadIdx.x;
    const int wid = tid >> 5;
    const int lane = tid & 31;

    const int strip = blockIdx.x;          // 0..31
    const int half  = blockIdx.y;          // 0..1
    const int b     = blockIdx.z;          // 0..15
    const int y0    = strip << 1;

    // zero the permanent border slots (px = -1 and 64) once
    if (tid < 80) {
        int t = tid / 40, rem = tid % 40;
        int m = rem / 10, r2 = rem % 10;
        int s = r2 / 5, q = r2 % 5;
        *(uint4*)(smem + t * XS_T + m * XS_M + (s ? 65 : 0) * 80 + q * 16) =
            make_uint4(0, 0, 0, 0);
    }

    const int wm = wid >> 1;               // 0..3  (co sub-tile)
    const int wn = wid & 1;                // 0..1  (image row)

    // lane-derived ldmatrix offsets
    const int a_off   = (lane & 15) * 80 + (lane >> 4) * 16;
    const int px_off  = (lane & 7) + ((lane >> 4) << 3);
    const int b_k_off = ((lane >> 3) & 1) * 16;

    float acc[2][8][4];
#pragma unroll
    for (int i = 0; i < 2; ++i)
#pragma unroll
        for (int j = 0; j < 8; ++j)
#pragma unroll
            for (int k = 0; k < 4; ++k) acc[i][j][k] = 0.0f;

    const uint32_t ws_b = sb + OFF_WS;

    for (int c0 = 0; c0 < 256; c0 += 32) {
        // ---- stage weights tap 0 -> buf 0 ----
#pragma unroll
        for (int it = 0; it < 2; ++it) {
            int idx = tid + it * 256;
            int co_l = idx >> 2, q = idx & 3;
            size_t off = (((size_t)(half * 128 + co_l)) << 8) + c0 + q * 8;
            char* d = smem + OFF_WS + co_l * 80 + q * 16;
            *(uint4*)d          = *(const uint4*)(g_wh + off);
            *(uint4*)(d + WS_T) = *(const uint4*)(g_wl + off);
        }
        // ---- stage input rows y0-1..y0+2, 32 ci ----
#pragma unroll
        for (int it = 0; it < 4; ++it) {
            int idx = tid + it * 256;
            int m = idx >> 8, rem = idx & 255, px = rem >> 2, q = rem & 3;
            int yi = y0 + m - 1;
            uint4 vh = make_uint4(0, 0, 0, 0), vl = vh;
            if ((unsigned)yi < 64u) {
                size_t off = ((((size_t)b * 64 + yi) * 64 + px) << 8) + c0 + q * 8;
                vh = *(const uint4*)(g_pth + off);
                vl = *(const uint4*)(g_ptl + off);
            }
            char* d = smem + m * XS_M + (px + 1) * 80 + q * 16;
            *(uint4*)d          = vh;
            *(uint4*)(d + XS_T) = vl;
        }
        __syncthreads();

#pragma unroll 1
        for (int tap = 0; tap < 9; ++tap) {
            const int buf = tap & 1;
            // ---- prefetch next tap's weights into other buffer ----
            if (tap < 8) {
#pragma unroll
                for (int it = 0; it < 2; ++it) {
                    int idx = tid + it * 256;
                    int co_l = idx >> 2, q = idx & 3;
                    size_t off = (((size_t)(tap + 1) * 256 + half * 128 + co_l) << 8)
                                 + c0 + q * 8;
                    char* d = smem + OFF_WS + (buf ^ 1) * WS_B + co_l * 80 + q * 16;
                    *(uint4*)d          = *(const uint4*)(g_wh + off);
                    *(uint4*)(d + WS_T) = *(const uint4*)(g_wl + off);
                }
            }
            // ---- compute ----
            const int dy = tap / 3, dx = tap - dy * 3;
            const int m = wn + dy;
            const uint32_t bb = sb + m * XS_M + (px_off + dx) * 80 + b_k_off;
            const uint32_t ab = ws_b + buf * WS_B + wm * 2560 + a_off;

#pragma unroll
            for (int ks = 0; ks < 2; ++ks) {
                uint32_t ah0[4], ah1[4], al0[4], al1[4];
                LDSM4(ah0, ab + ks * 32);
                LDSM4(ah1, ab + 1280 + ks * 32);
                LDSM4(al0, ab + WS_T + ks * 32);
                LDSM4(al1, ab + WS_T + 1280 + ks * 32);
#pragma unroll
                for (int nb2 = 0; nb2 < 4; ++nb2) {
                    uint32_t bh[4], bl[4];
                    uint32_t bp = bb + nb2 * 1280 + ks * 32;
                    LDSM4(bh, bp);
                    LDSM4(bl, bp + XS_T);
                    // hh
                    MMA16816(acc[0][2 * nb2],     ah0, bh[0], bh[1]);
                    MMA16816(acc[0][2 * nb2 + 1], ah0, bh[2], bh[3]);
                    MMA16816(acc[1][2 * nb2],     ah1, bh[0], bh[1]);
                    MMA16816(acc[1][2 * nb2 + 1], ah1, bh[2], bh[3]);
                    // lh
                    MMA16816(acc[0][2 * nb2],     al0, bh[0], bh[1]);
                    MMA16816(acc[0][2 * nb2 + 1], al0, bh[2], bh[3]);
                    MMA16816(acc[1][2 * nb2],     al1, bh[0], bh[1]);
                    MMA16816(acc[1][2 * nb2 + 1], al1, bh[2], bh[3]);
                    // hl
                    MMA16816(acc[0][2 * nb2],     ah0, bl[0], bl[1]);
                    MMA16816(acc[0][2 * nb2 + 1], ah0, bl[2], bl[3]);
                    MMA16816(acc[1][2 * nb2],     ah1, bl[0], bl[1]);
                    MMA16816(acc[1][2 * nb2 + 1], ah1, bl[2], bl[3]);
                }
            }
            __syncthreads();
        }
    }

    // ---- epilogue ----
#pragma unroll
    for (int mf = 0; mf < 2; ++mf) {
        int co = half * 128 + wm * 32 + mf * 16 + (lane >> 2);
        float bv0 = bias[co];
        float bv1 = bias[co + 8];
        float* o0 = out + (((size_t)b * 256 + co) << 12) + ((y0 + wn) << 6);
        float* o1 = o0 + (8 << 12);
#pragma unroll
        for (int nb = 0; nb < 8; ++nb) {
            int x = nb * 8 + (lane & 3) * 2;
            *(float2*)(o0 + x) =
                make_float2(acc[mf][nb][0] + bv0, acc[mf][nb][1] + bv0);
            *(float2*)(o1 + x) =
                make_float2(acc[mf][nb][2] + bv1, acc[mf][nb][3] + bv1);
        }
    }
}

// ---------------- launch ----------------
extern "C" void kernel_launch(void* const* d_in, const int* in_sizes, int n_in,
                              void* d_out, int out_size) {
    const float* x    = (const float*)d_in[0];
    const float* w    = (const float*)d_in[1];
    const float* bias = (const float*)d_in[2];
    float* out = (float*)d_out;

    static int smem_set = 0;
    if (!smem_set) {
        cudaFuncSetAttribute(conv_mma_kernel,
                             cudaFuncAttributeMaxDynamicSharedMemorySize,
                             SMEM_TOTAL);
        smem_set = 1;
    }

    init_keys_kernel<<<1, 64>>>();
    energy_argmax_kernel<<<512, 256>>>(x);
    pool_split_kernel<<<1024, 256>>>(x);
    wsplit_kernel<<<2304, 256>>>(w);

    dim3 grid(32, 2, 16);   // row strips, co halves, batch
    conv_mma_kernel<<<grid, 256, SMEM_TOTAL>>>(bias, out);
}

// round 7
// speedup vs baseline: 6.0900x; 1.1480x over previous
#include <cuda_runtime.h>
#include <cstdint>

// ---------------------------------------------------------------------------
// G2Conv2d4 via tf32 mma.sync (base PTX ISA; sm_103 non-'a' target).
//   argmax -> pooled = in-rect ? max(x^2, landmark) : x^2  (one-hot collapse)
//   conv3x3 = 9 shifted GEMMs, single-pass tf32 with cvt.rna pre-rounding.
// CTA: 128 co x 4 rows x 64 px, 512 threads (16 warps, 4m x 4n).
// A frags: fragment-major in gmem -> memcpy stage -> 1x LDS.128 each.
// B frags: ci pairs (k,k+4) interleaved in gmem -> 1x LDS.64 each;
//          px axis has 66 slots with permanent zero borders (SAME pad free),
//          dx tap shift = slot offset. Row stride 40 floats (conflict-free).
// ---------------------------------------------------------------------------

__device__ unsigned long long g_part[512];                 // argmax partials
__device__ __align__(16) float g_pt[16ull * 64 * 64 * 256]; // pooled tf32 67MB
__device__ __align__(16) float g_wf[9 * 32 * 16 * 128];     // frag-major w

__device__ __forceinline__ uint32_t smem_u32(const void* p) {
    uint32_t a;
    asm("{ .reg .u64 t; cvta.to.shared.u64 t, %1; cvt.u32.u64 %0, t; }"
        : "=r"(a) : "l"(p));
    return a;
}
__device__ __forceinline__ float rna_tf32(float v) {
    uint32_t r;
    asm("cvt.rna.tf32.f32 %0, %1;" : "=r"(r) : "f"(v));
    return __uint_as_float(r);
}

#define LDS128U(r, addr)                                                      \
    asm volatile("ld.shared.v4.b32 {%0,%1,%2,%3}, [%4];"                      \
                 : "=r"((r)[0]), "=r"((r)[1]), "=r"((r)[2]), "=r"((r)[3])     \
                 : "r"(addr))
#define LDS64U(r, addr)                                                       \
    asm volatile("ld.shared.v2.b32 {%0,%1}, [%2];"                            \
                 : "=r"((r)[0]), "=r"((r)[1]) : "r"(addr))
#define MMA_TF32(d, a, b)                                                     \
    asm volatile(                                                             \
        "mma.sync.aligned.m16n8k8.row.col.f32.tf32.tf32.f32 "                 \
        "{%0,%1,%2,%3}, {%4,%5,%6,%7}, {%8,%9}, {%0,%1,%2,%3};"               \
        : "+f"((d)[0]), "+f"((d)[1]), "+f"((d)[2]), "+f"((d)[3])              \
        : "r"((a)[0]), "r"((a)[1]), "r"((a)[2]), "r"((a)[3]),                 \
          "r"((b)[0]), "r"((b)[1]))

// ---------------- Kernel 1: energy argmax partials ----------------
__global__ void energy_argmax_kernel(const float* __restrict__ x) {
    int bq    = blockIdx.x >> 3;
    int slice = blockIdx.x & 7;
    int b = bq >> 2, q = bq & 3;
    const float* xb = x + (((size_t)b * 256 + q * 64) << 12);

    unsigned long long best = 0ull;
    int p0 = slice * 512;
    for (int p = p0 + threadIdx.x; p < p0 + 512; p += 256) {
        float s = 0.0f;
#pragma unroll 8
        for (int c = 0; c < 64; ++c) {
            float v = xb[((size_t)c << 12) + p];
            s = fmaf(v, v, s);
        }
        unsigned long long key =
            ((unsigned long long)__float_as_uint(s) << 32) |
            (unsigned long long)(unsigned)(~p);
        if (key > best) best = key;
    }
    __shared__ unsigned long long sk[256];
    sk[threadIdx.x] = best;
    __syncthreads();
    for (int off = 128; off; off >>= 1) {
        if (threadIdx.x < off) {
            unsigned long long o = sk[threadIdx.x + off];
            if (o > sk[threadIdx.x]) sk[threadIdx.x] = o;
        }
        __syncthreads();
    }
    if (threadIdx.x == 0) g_part[blockIdx.x] = sk[0];
}

// ---------------- Kernel 2: pooled x^2 -> tf32-rounded fp32 -------------
// layout: [((b*64+y)*64 + px)*256 + ci'], ci' = pair-interleave within 8:
// j<4 -> 2j, else 2(j-4)+1 (so B frag (k,k+4) is one LDS.64).
__global__ void pool_kernel(const float* __restrict__ x, int part) {
    int bid = blockIdx.x + part * 512;     // b*64 + y
    int b = bid >> 6, y = bid & 63;
    int ci = threadIdx.x;
    int q = ci >> 6;
    int bq = (b << 2) | q;

    unsigned long long key = 0ull;
#pragma unroll
    for (int s = 0; s < 8; ++s) {
        unsigned long long o = g_part[bq * 8 + s];
        if (o > key) key = o;
    }
    int p = (int)(~(unsigned)key) & 4095;
    int r = p >> 6, c = p & 63;

    const float* xc = x + ((size_t)(b * 256 + ci) << 12);
    float lv = xc[(r << 6) | c];
    lv *= lv;
    bool ch = (q < 2) ? (y <= r) : (y >= r);
    bool leftW = ((q & 1) == 0);

    int j = ci & 7;
    int ci_perm = (ci & ~7) + ((j < 4) ? (j << 1) : (((j - 4) << 1) + 1));

    const float4* row4 = (const float4*)(xc + (y << 6));
    size_t obase = (((size_t)bid << 6) << 8) + ci_perm;

#pragma unroll 4
    for (int i = 0; i < 16; ++i) {
        float4 v = row4[i];
        int x0 = i << 2;
        float s[4] = {v.x * v.x, v.y * v.y, v.z * v.z, v.w * v.w};
        if (ch) {
#pragma unroll
            for (int jj = 0; jj < 4; ++jj)
                if (leftW ? (x0 + jj <= c) : (x0 + jj >= c))
                    s[jj] = fmaxf(s[jj], lv);
        }
#pragma unroll
        for (int jj = 0; jj < 4; ++jj)
            g_pt[obase + ((size_t)(x0 + jj) << 8)] = rna_tf32(s[jj]);
    }
}

// ---------------- Kernel 3: weights -> fragment-major tf32 --------------
// g_wf[((tap*32 + k8)*16 + ct)*128 + lane*4 + r]
// frag elem: co = ct*16 + (lane>>2) + 8*(r&1), ci = k8*8 + (lane&3) + 4*(r>>1)
__global__ void wprep_kernel(const float* __restrict__ w, int part) {
    int idx = (blockIdx.x + part * 1152) * 256 + threadIdx.x;
    int r    = idx & 3;
    int lane = (idx >> 2) & 31;
    int ct   = (idx >> 7) & 15;
    int k8   = (idx >> 11) & 31;
    int tap  = idx >> 16;
    int co = ct * 16 + (lane >> 2) + ((r & 1) << 3);
    int ci = k8 * 8 + (lane & 3) + ((r >> 1) << 2);
    g_wf[idx] = rna_tf32(w[((size_t)co * 256 + ci) * 9 + tap]);
}

// ---------------- Kernel 4: tf32 mma conv ----------------
// smem: xs[row(6)][slot(66)][40 floats] then ws[buf(2)][16KB frag-major]
#define XS_SLOT 160              // 40 floats
#define XS_M (66 * XS_SLOT)      // 10560
#define OFF_WS (6 * XS_M)        // 63360
#define WS_B 16384
#define SMEM_TOTAL (OFF_WS + 2 * WS_B)   // 96128

__global__ __launch_bounds__(512, 1)
void conv_mma_kernel(const float* __restrict__ bias, float* __restrict__ out) {
    extern __shared__ __align__(16) char smem[];
    const uint32_t sb = smem_u32(smem);
    const int tid = threadIdx.x;
    const int wid = tid >> 5;
    const int lane = tid & 31;

    const int strip = blockIdx.x;          // 0..15 -> 4 rows each
    const int half  = blockIdx.y;          // 0..1
    const int b     = blockIdx.z;          // 0..15
    const int y0    = strip << 2;

    // permanent zero borders: slots 0 and 65, 6 rows, 10 uint4 each
    if (tid < 120) {
        int m = tid / 20, rem = tid % 20;
        int s = rem / 10, qq = rem % 10;
        *(uint4*)(smem + m * XS_M + (s ? 65 : 0) * XS_SLOT + qq * 16) =
            make_uint4(0, 0, 0, 0);
    }

    const int wm = wid >> 2;               // 0..3 (co 32-tile)
    const int wn = wid & 3;                // 0..3 (output row)

    float acc[2][8][4];
#pragma unroll
    for (int i = 0; i < 2; ++i)
#pragma unroll
        for (int jj = 0; jj < 8; ++jj)
#pragma unroll
            for (int k = 0; k < 4; ++k) acc[i][jj][k] = 0.0f;

    const uint32_t ws0 = sb + OFF_WS;
    const int ln4 = lane & 3, lq = lane >> 2;

    for (int c0 = 0; c0 < 256; c0 += 32) {
        // ---- stage weights tap0 -> buf0 (coalesced frag-major memcpy) ----
#pragma unroll
        for (int it = 0; it < 2; ++it) {
            int idx = tid + it * 512;                 // 1024 uint4
            int k8i = idx >> 8, rem = idx & 255;
            const uint4* g = (const uint4*)g_wf +
                (((size_t)(0 * 32 + (c0 >> 3) + k8i) * 16 + half * 8) << 5) + rem;
            *(uint4*)(smem + OFF_WS + k8i * 4096 + rem * 16) = *g;
        }
        // ---- stage input rows y0-1..y0+4 (6 rows) ----
#pragma unroll
        for (int it = 0; it < 6; ++it) {
            int idx = tid + it * 512;                 // 3072 uint4
            int m = idx >> 9, rem = idx & 511;
            int px = rem >> 3, qq = rem & 7;
            int yi = y0 + m - 1;
            uint4 v = make_uint4(0, 0, 0, 0);
            if ((unsigned)yi < 64u) {
                size_t off = ((((size_t)b * 64 + yi) * 64 + px) << 8) + c0;
                v = ((const uint4*)(g_pt + off))[qq];
            }
            *(uint4*)(smem + m * XS_M + (px + 1) * XS_SLOT + qq * 16) = v;
        }
        __syncthreads();

#pragma unroll 1
        for (int tap = 0; tap < 9; ++tap) {
            const int buf = tap & 1;
            // ---- prefetch next tap's weights into other buffer ----
            if (tap < 8) {
#pragma unroll
                for (int it = 0; it < 2; ++it) {
                    int idx = tid + it * 512;
                    int k8i = idx >> 8, rem = idx & 255;
                    const uint4* g = (const uint4*)g_wf +
                        (((size_t)((tap + 1) * 32 + (c0 >> 3) + k8i) * 16 +
                          half * 8) << 5) + rem;
                    *(uint4*)(smem + OFF_WS + (buf ^ 1) * WS_B +
                              k8i * 4096 + rem * 16) = *g;
                }
            }
            // ---- compute ----
            const int dy = tap / 3, dx = tap - dy * 3;
            const uint32_t bb = sb + (wn + dy) * XS_M +
                                (lq + dx) * XS_SLOT + ln4 * 8;
            const uint32_t ab = ws0 + buf * WS_B + (wm * 2) * 512 + lane * 16;

#pragma unroll
            for (int ks = 0; ks < 4; ++ks) {
                uint32_t a0[4], a1[4];
                LDS128U(a0, ab + ks * 4096);
                LDS128U(a1, ab + ks * 4096 + 512);
#pragma unroll
                for (int nb = 0; nb < 8; ++nb) {
                    uint32_t bfr[2];
                    LDS64U(bfr, bb + nb * (8 * XS_SLOT) + ks * 32);
                    MMA_TF32(acc[0][nb], a0, bfr);
                    MMA_TF32(acc[1][nb], a1, bfr);
                }
            }
            __syncthreads();
        }
    }

    // ---- epilogue ----
#pragma unroll
    for (int mf = 0; mf < 2; ++mf) {
        int co = half * 128 + wm * 32 + mf * 16 + lq;
        float bv0 = bias[co];
        float bv1 = bias[co + 8];
        float* o0 = out + (((size_t)b * 256 + co) << 12) + ((y0 + wn) << 6);
        float* o1 = o0 + (8 << 12);
#pragma unroll
        for (int nb = 0; nb < 8; ++nb) {
            int xp = nb * 8 + ln4 * 2;
            *(float2*)(o0 + xp) =
                make_float2(acc[mf][nb][0] + bv0, acc[mf][nb][1] + bv0);
            *(float2*)(o1 + xp) =
                make_float2(acc[mf][nb][2] + bv1, acc[mf][nb][3] + bv1);
        }
    }
}

// ---------------- launch ----------------
extern "C" void kernel_launch(void* const* d_in, const int* in_sizes, int n_in,
                              void* d_out, int out_size) {
    const float* x    = (const float*)d_in[0];
    const float* w    = (const float*)d_in[1];
    const float* bias = (const float*)d_in[2];
    float* out = (float*)d_out;

    static int smem_set = 0;
    if (!smem_set) {
        cudaFuncSetAttribute(conv_mma_kernel,
                             cudaFuncAttributeMaxDynamicSharedMemorySize,
                             SMEM_TOTAL);
        smem_set = 1;
    }

    energy_argmax_kernel<<<512, 256>>>(x);     // launch 0
    pool_kernel<<<512, 256>>>(x, 0);           // launch 1
    pool_kernel<<<512, 256>>>(x, 1);           // launch 2
    wprep_kernel<<<1152, 256>>>(w, 0);         // launch 3
    wprep_kernel<<<1152, 256>>>(w, 1);         // launch 4

    dim3 grid(16, 2, 16);                      // strips, co halves, batch
    conv_mma_kernel<<<grid, 512, SMEM_TOTAL>>>(bias, out);   // launch 5
}

// round 9
// speedup vs baseline: 9.7575x; 1.6022x over previous
#include <cuda_runtime.h>
#include <cuda_fp16.h>
#include <cstdint>

// ---------------------------------------------------------------------------
// G2Conv2d4 via single-pass fp16 mma.sync m16n8k16 (base PTX ISA, sm_103).
//   argmax -> pooled = in-rect ? max(x^2, landmark) : x^2  (one-hot collapse)
//   conv3x3 = 9 shifted GEMMs. fp16 (11-bit mantissa ~= tf32 precision) with
//   fp32 accumulate: rel_err ~3e-4, half the MMA instructions of tf32 k8.
// CTA: 128 co x 4 rows x 64 px, 512 threads (16 warps, 4m x 4n).
// A frags: fragment-major fp16 in gmem -> memcpy stage -> 1x LDS.128 each.
// B frags: ci' interleave [2t,2t+1,2t+8,2t+9] per 16-group -> 1x LDS.64;
//          px axis 66 slots w/ permanent zero borders; slot stride 96B
//          (all-32-bank conflict-free for the LDS.64 pattern).
// (Round 9 = identical resubmission of Round 8: bench failure was a GB300
//  container-acquisition error; the kernel never ran.)
// ---------------------------------------------------------------------------

__device__ unsigned long long g_part[512];                    // argmax partials
__device__ __align__(16) __half g_pt[16ull * 64 * 64 * 256];  // pooled 33.5MB
__device__ __align__(16) uint32_t g_wf[9 * 16 * 16 * 32 * 4]; // frag-major w

__device__ __forceinline__ uint32_t smem_u32(const void* p) {
    uint32_t a;
    asm("{ .reg .u64 t; cvta.to.shared.u64 t, %1; cvt.u32.u64 %0, t; }"
        : "=r"(a) : "l"(p));
    return a;
}

#define LDS128U(r, addr)                                                      \
    asm volatile("ld.shared.v4.b32 {%0,%1,%2,%3}, [%4];"                      \
                 : "=r"((r)[0]), "=r"((r)[1]), "=r"((r)[2]), "=r"((r)[3])     \
                 : "r"(addr))
#define LDS64U(r, addr)                                                       \
    asm volatile("ld.shared.v2.b32 {%0,%1}, [%2];"                            \
                 : "=r"((r)[0]), "=r"((r)[1]) : "r"(addr))
#define MMA_F16(d, a, b)                                                      \
    asm volatile(                                                             \
        "mma.sync.aligned.m16n8k16.row.col.f32.f16.f16.f32 "                  \
        "{%0,%1,%2,%3}, {%4,%5,%6,%7}, {%8,%9}, {%0,%1,%2,%3};"               \
        : "+f"((d)[0]), "+f"((d)[1]), "+f"((d)[2]), "+f"((d)[3])              \
        : "r"((a)[0]), "r"((a)[1]), "r"((a)[2]), "r"((a)[3]),                 \
          "r"((b)[0]), "r"((b)[1]))

// ---------------- Kernel 1: energy argmax partials ----------------
__global__ void energy_argmax_kernel(const float* __restrict__ x) {
    int bq    = blockIdx.x >> 3;
    int slice = blockIdx.x & 7;
    int b = bq >> 2, q = bq & 3;
    const float* xb = x + (((size_t)b * 256 + q * 64) << 12);

    unsigned long long best = 0ull;
    int p0 = slice * 512;
    for (int p = p0 + threadIdx.x; p < p0 + 512; p += 256) {
        float s = 0.0f;
#pragma unroll 8
        for (int c = 0; c < 64; ++c) {
            float v = xb[((size_t)c << 12) + p];
            s = fmaf(v, v, s);
        }
        unsigned long long key =
            ((unsigned long long)__float_as_uint(s) << 32) |
            (unsigned long long)(unsigned)(~p);
        if (key > best) best = key;
    }
    __shared__ unsigned long long sk[256];
    sk[threadIdx.x] = best;
    __syncthreads();
    for (int off = 128; off; off >>= 1) {
        if (threadIdx.x < off) {
            unsigned long long o = sk[threadIdx.x + off];
            if (o > sk[threadIdx.x]) sk[threadIdx.x] = o;
        }
        __syncthreads();
    }
    if (threadIdx.x == 0) g_part[blockIdx.x] = sk[0];
}

// ---------------- Kernel 2: pooled x^2 -> fp16, B-frag ci' interleave ----
// layout: [((b*64+y)*64 + px)*256 + ci'], ci' within each 16-group:
//   pos(j) = 4*((j&7)>>1) + 2*(j>>3) + (j&1)   (so LDS.64 = {2t,2t+1,2t+8,2t+9})
__global__ void pool_kernel(const float* __restrict__ x) {
    int bid = blockIdx.x;              // b*64 + y
    int b = bid >> 6, y = bid & 63;
    int ci = threadIdx.x;
    int q = ci >> 6;
    int bq = (b << 2) | q;

    unsigned long long key = 0ull;
#pragma unroll
    for (int s = 0; s < 8; ++s) {
        unsigned long long o = g_part[bq * 8 + s];
        if (o > key) key = o;
    }
    int p = (int)(~(unsigned)key) & 4095;
    int r = p >> 6, c = p & 63;

    const float* xc = x + ((size_t)(b * 256 + ci) << 12);
    float lv = xc[(r << 6) | c];
    lv *= lv;
    bool ch = (q < 2) ? (y <= r) : (y >= r);
    bool leftW = ((q & 1) == 0);

    int j = ci & 15;
    int ci_perm = (ci & ~15) + 4 * ((j & 7) >> 1) + 2 * (j >> 3) + (j & 1);

    const float4* row4 = (const float4*)(xc + (y << 6));
    size_t obase = (((size_t)bid << 6) << 8) + ci_perm;

#pragma unroll 4
    for (int i = 0; i < 16; ++i) {
        float4 v = row4[i];
        int x0 = i << 2;
        float s[4] = {v.x * v.x, v.y * v.y, v.z * v.z, v.w * v.w};
        if (ch) {
#pragma unroll
            for (int jj = 0; jj < 4; ++jj)
                if (leftW ? (x0 + jj <= c) : (x0 + jj >= c))
                    s[jj] = fmaxf(s[jj], lv);
        }
#pragma unroll
        for (int jj = 0; jj < 4; ++jj)
            g_pt[obase + ((size_t)(x0 + jj) << 8)] = __float2half_rn(s[jj]);
    }
}

// ---------------- Kernel 3: weights -> fragment-major fp16 --------------
// g_wf u32 idx: (((tap*16 + k16)*16 + ct)*32 + lane)*4 + u
// u: reg index 0..3; halves p=0,1:
//   co = ct*16 + (lane>>2) + 8*(u&1);  ci = k16*16 + 2*(lane&3) + 8*(u>>1) + p
__global__ void wprep_kernel(const float* __restrict__ w) {
    int idx = blockIdx.x * 256 + threadIdx.x;     // 1152 blocks = 294912
    int u    = idx & 3;
    int lane = (idx >> 2) & 31;
    int ct   = (idx >> 7) & 15;
    int k16  = (idx >> 11) & 15;
    int tap  = idx >> 15;
    int co  = ct * 16 + (lane >> 2) + ((u & 1) << 3);
    int ci0 = k16 * 16 + ((lane & 3) << 1) + ((u >> 1) << 3);
    unsigned h0 = __half_as_ushort(
        __float2half_rn(w[((size_t)co * 256 + ci0) * 9 + tap]));
    unsigned h1 = __half_as_ushort(
        __float2half_rn(w[((size_t)co * 256 + ci0 + 1) * 9 + tap]));
    g_wf[idx] = (h1 << 16) | h0;
}

// ---------------- Kernel 4: fp16 mma conv ----------------
// smem: xs[row(6)][slot(66)][96B: 32 ci' fp16 + 32B pad] then
//       ws[buf(2)][8KB frag-major: 16 tiles (2 k16 x 8 ct) x 512B]
#define XS_SLOT 96
#define XS_M (66 * XS_SLOT)        // 6336
#define OFF_WS (6 * XS_M)          // 38016
#define WS_B 8192
#define SMEM_TOTAL (OFF_WS + 2 * WS_B)   // 54400

__global__ __launch_bounds__(512, 1)
void conv_mma_kernel(const float* __restrict__ bias, float* __restrict__ out) {
    extern __shared__ __align__(16) char smem[];
    const uint32_t sb = smem_u32(smem);
    const int tid = threadIdx.x;
    const int wid = tid >> 5;
    const int lane = tid & 31;

    const int strip = blockIdx.x;          // 0..15 -> 4 rows each
    const int half  = blockIdx.y;          // 0..1
    const int b     = blockIdx.z;          // 0..15
    const int y0    = strip << 2;

    // permanent zero borders: slots 0 and 65, 6 rows, 4 uint4 (64B) each
    if (tid < 48) {
        int m = tid / 8, rem = tid % 8;
        int s = rem / 4, qq = rem % 4;
        *(uint4*)(smem + m * XS_M + (s ? 65 : 0) * XS_SLOT + qq * 16) =
            make_uint4(0, 0, 0, 0);
    }

    const int wm = wid >> 2;               // 0..3 (co 32-tile)
    const int wn = wid & 3;                // 0..3 (output row)

    float acc[2][8][4];
#pragma unroll
    for (int i = 0; i < 2; ++i)
#pragma unroll
        for (int jj = 0; jj < 8; ++jj)
#pragma unroll
            for (int k = 0; k < 4; ++k) acc[i][jj][k] = 0.0f;

    const uint32_t ws0 = sb + OFF_WS;
    const int ln4 = lane & 3, lq = lane >> 2;

    for (int c0 = 0; c0 < 256; c0 += 32) {
        const int k16b = c0 >> 4;
        // ---- stage weights tap 0 -> buf 0 (512 uint4 memcpy) ----
        {
            int k16i = tid >> 8, rem = tid & 255;
            int ct8 = rem >> 5, ln = rem & 31;
            const uint4* g = (const uint4*)g_wf +
                (((size_t)(0 * 16 + k16b + k16i) * 16 + half * 8 + ct8) << 5) + ln;
            *(uint4*)(smem + OFF_WS + tid * 16) = *g;
        }
        // ---- stage input rows y0-1..y0+4 (6 rows x 64px x 32ci fp16) ----
#pragma unroll
        for (int it = 0; it < 3; ++it) {
            int idx = tid + it * 512;                 // 1536 uint4
            int m = idx >> 8, rem = idx & 255;
            int px = rem >> 2, qq = rem & 3;
            int yi = y0 + m - 1;
            uint4 v = make_uint4(0, 0, 0, 0);
            if ((unsigned)yi < 64u) {
                size_t off = ((((size_t)b * 64 + yi) * 64 + px) << 8) + c0 + qq * 8;
                v = *(const uint4*)(g_pt + off);
            }
            *(uint4*)(smem + m * XS_M + (px + 1) * XS_SLOT + qq * 16) = v;
        }
        __syncthreads();

#pragma unroll 1
        for (int tap = 0; tap < 9; ++tap) {
            const int buf = tap & 1;
            // ---- prefetch next tap's weights into other buffer ----
            if (tap < 8) {
                int k16i = tid >> 8, rem = tid & 255;
                int ct8 = rem >> 5, ln = rem & 31;
                const uint4* g = (const uint4*)g_wf +
                    (((size_t)((tap + 1) * 16 + k16b + k16i) * 16 +
                      half * 8 + ct8) << 5) + ln;
                *(uint4*)(smem + OFF_WS + (buf ^ 1) * WS_B + tid * 16) = *g;
            }
            // ---- compute ----
            const int dy = tap / 3, dx = tap - dy * 3;
            const uint32_t bb = sb + (wn + dy) * XS_M +
                                (lq + dx) * XS_SLOT + ln4 * 8;
            const uint32_t ab = ws0 + buf * WS_B + (wm * 2) * 512 + lane * 16;

#pragma unroll
            for (int ks = 0; ks < 2; ++ks) {
                uint32_t a0[4], a1[4];
                LDS128U(a0, ab + ks * 4096);
                LDS128U(a1, ab + ks * 4096 + 512);
#pragma unroll
                for (int nb = 0; nb < 8; ++nb) {
                    uint32_t bfr[2];
                    LDS64U(bfr, bb + nb * (8 * XS_SLOT) + ks * 32);
                    MMA_F16(acc[0][nb], a0, bfr);
                    MMA_F16(acc[1][nb], a1, bfr);
                }
            }
            __syncthreads();
        }
    }

    // ---- epilogue ----
#pragma unroll
    for (int mf = 0; mf < 2; ++mf) {
        int co = half * 128 + wm * 32 + mf * 16 + lq;
        float bv0 = bias[co];
        float bv1 = bias[co + 8];
        float* o0 = out + (((size_t)b * 256 + co) << 12) + ((y0 + wn) << 6);
        float* o1 = o0 + (8 << 12);
#pragma unroll
        for (int nb = 0; nb < 8; ++nb) {
            int xp = nb * 8 + ln4 * 2;
            *(float2*)(o0 + xp) =
                make_float2(acc[mf][nb][0] + bv0, acc[mf][nb][1] + bv0);
            *(float2*)(o1 + xp) =
                make_float2(acc[mf][nb][2] + bv1, acc[mf][nb][3] + bv1);
        }
    }
}

// ---------------- launch ----------------
extern "C" void kernel_launch(void* const* d_in, const int* in_sizes, int n_in,
                              void* d_out, int out_size) {
    const float* x    = (const float*)d_in[0];
    const float* w    = (const float*)d_in[1];
    const float* bias = (const float*)d_in[2];
    float* out = (float*)d_out;

    static int smem_set = 0;
    if (!smem_set) {
        cudaFuncSetAttribute(conv_mma_kernel,
                             cudaFuncAttributeMaxDynamicSharedMemorySize,
                             SMEM_TOTAL);
        smem_set = 1;
    }

    energy_argmax_kernel<<<512, 256>>>(x);     // launch 0
    pool_kernel<<<1024, 256>>>(x);             // launch 1
    wprep_kernel<<<1152, 256>>>(w);            // launch 2

    dim3 grid(16, 2, 16);                      // strips, co halves, batch
    conv_mma_kernel<<<grid, 512, SMEM_TOTAL>>>(bias, out);   // launch 3
}

// round 10
// speedup vs baseline: 14.0568x; 1.4406x over previous
#include <cuda_runtime.h>
#include <cuda_fp16.h>
#include <cstdint>

// ---------------------------------------------------------------------------
// G2Conv2d4, fp16 mma.sync m16n8k16, chunk-resident weights + cp.async
// double-buffering (Round 10).
//   argmax -> pooled = in-rect ? max(x^2, landmark) : x^2  (one-hot collapse)
//   conv3x3 = 9 shifted GEMMs, fp16 inputs (11-bit mantissa), fp32 accum.
// CTA: 128 co x 4 rows x 64 px, 512 threads (16 warps, 4m x 4n).
// Per ci-chunk (32 ci): ALL 9 taps' weights (72KB) + input tile (38KB) staged
// together via cp.async into one of two buffers; ONE barrier per chunk; the
// 9-tap MMA stream runs uninterrupted. dx shift = px-slot offset into a
// 66-slot axis with permanent zero borders (SAME padding for free).
// ---------------------------------------------------------------------------

__device__ unsigned long long g_part[512];                    // argmax partials
__device__ __align__(16) __half g_pt[16ull * 64 * 64 * 256];  // pooled 33.5MB
__device__ __align__(16) uint32_t g_wf[9 * 16 * 16 * 32 * 4]; // frag-major w

__device__ __forceinline__ uint32_t smem_u32(const void* p) {
    uint32_t a;
    asm("{ .reg .u64 t; cvta.to.shared.u64 t, %1; cvt.u32.u64 %0, t; }"
        : "=r"(a) : "l"(p));
    return a;
}

#define LDS128U(r, addr)                                                      \
    asm volatile("ld.shared.v4.b32 {%0,%1,%2,%3}, [%4];"                      \
                 : "=r"((r)[0]), "=r"((r)[1]), "=r"((r)[2]), "=r"((r)[3])     \
                 : "r"(addr))
#define LDS64U(r, addr)                                                       \
    asm volatile("ld.shared.v2.b32 {%0,%1}, [%2];"                            \
                 : "=r"((r)[0]), "=r"((r)[1]) : "r"(addr))
#define MMA_F16(d, a, b)                                                      \
    asm volatile(                                                             \
        "mma.sync.aligned.m16n8k16.row.col.f32.f16.f16.f32 "                  \
        "{%0,%1,%2,%3}, {%4,%5,%6,%7}, {%8,%9}, {%0,%1,%2,%3};"               \
        : "+f"((d)[0]), "+f"((d)[1]), "+f"((d)[2]), "+f"((d)[3])              \
        : "r"((a)[0]), "r"((a)[1]), "r"((a)[2]), "r"((a)[3]),                 \
          "r"((b)[0]), "r"((b)[1]))
#define CP16(dst, src, sz)                                                    \
    asm volatile("cp.async.cg.shared.global [%0], [%1], 16, %2;"              \
                 :: "r"(dst), "l"(src), "r"(sz))
#define CP_COMMIT() asm volatile("cp.async.commit_group;" ::: "memory")
#define CP_WAIT0()  asm volatile("cp.async.wait_group 0;" ::: "memory")

// ---------------- Kernel 1: energy argmax partials ----------------
__global__ void energy_argmax_kernel(const float* __restrict__ x) {
    int bq    = blockIdx.x >> 3;
    int slice = blockIdx.x & 7;
    int b = bq >> 2, q = bq & 3;
    const float* xb = x + (((size_t)b * 256 + q * 64) << 12);

    unsigned long long best = 0ull;
    int p0 = slice * 512;
    for (int p = p0 + threadIdx.x; p < p0 + 512; p += 256) {
        float s = 0.0f;
#pragma unroll 8
        for (int c = 0; c < 64; ++c) {
            float v = xb[((size_t)c << 12) + p];
            s = fmaf(v, v, s);
        }
        unsigned long long key =
            ((unsigned long long)__float_as_uint(s) << 32) |
            (unsigned long long)(unsigned)(~p);
        if (key > best) best = key;
    }
    __shared__ unsigned long long sk[256];
    sk[threadIdx.x] = best;
    __syncthreads();
    for (int off = 128; off; off >>= 1) {
        if (threadIdx.x < off) {
            unsigned long long o = sk[threadIdx.x + off];
            if (o > sk[threadIdx.x]) sk[threadIdx.x] = o;
        }
        __syncthreads();
    }
    if (threadIdx.x == 0) g_part[blockIdx.x] = sk[0];
}

// ---------------- Kernel 2: pooled x^2 -> fp16, B-frag ci' interleave ----
// layout: [((b*64+y)*64 + px)*256 + ci'], ci' within each 16-group:
//   pos(j) = 4*((j&7)>>1) + 2*(j>>3) + (j&1)  (LDS.64 = {2t,2t+1,2t+8,2t+9})
__global__ void pool_kernel(const float* __restrict__ x) {
    int bid = blockIdx.x;              // b*64 + y
    int b = bid >> 6, y = bid & 63;
    int ci = threadIdx.x;
    int q = ci >> 6;
    int bq = (b << 2) | q;

    unsigned long long key = 0ull;
#pragma unroll
    for (int s = 0; s < 8; ++s) {
        unsigned long long o = g_part[bq * 8 + s];
        if (o > key) key = o;
    }
    int p = (int)(~(unsigned)key) & 4095;
    int r = p >> 6, c = p & 63;

    const float* xc = x + ((size_t)(b * 256 + ci) << 12);
    float lv = xc[(r << 6) | c];
    lv *= lv;
    bool ch = (q < 2) ? (y <= r) : (y >= r);
    bool leftW = ((q & 1) == 0);

    int j = ci & 15;
    int ci_perm = (ci & ~15) + 4 * ((j & 7) >> 1) + 2 * (j >> 3) + (j & 1);

    const float4* row4 = (const float4*)(xc + (y << 6));
    size_t obase = (((size_t)bid << 6) << 8) + ci_perm;

#pragma unroll 4
    for (int i = 0; i < 16; ++i) {
        float4 v = row4[i];
        int x0 = i << 2;
        float s[4] = {v.x * v.x, v.y * v.y, v.z * v.z, v.w * v.w};
        if (ch) {
#pragma unroll
            for (int jj = 0; jj < 4; ++jj)
                if (leftW ? (x0 + jj <= c) : (x0 + jj >= c))
                    s[jj] = fmaxf(s[jj], lv);
        }
#pragma unroll
        for (int jj = 0; jj < 4; ++jj)
            g_pt[obase + ((size_t)(x0 + jj) << 8)] = __float2half_rn(s[jj]);
    }
}

// ---------------- Kernel 3: weights -> fragment-major fp16 --------------
// g_wf u32 idx: (((tap*16 + k16)*16 + ct)*32 + lane)*4 + u
//   co = ct*16 + (lane>>2) + 8*(u&1);  ci = k16*16 + 2*(lane&3) + 8*(u>>1) + p
__global__ void wprep_kernel(const float* __restrict__ w) {
    int idx = blockIdx.x * 256 + threadIdx.x;     // 1152 blocks = 294912
    int u    = idx & 3;
    int lane = (idx >> 2) & 31;
    int ct   = (idx >> 7) & 15;
    int k16  = (idx >> 11) & 15;
    int tap  = idx >> 15;
    int co  = ct * 16 + (lane >> 2) + ((u & 1) << 3);
    int ci0 = k16 * 16 + ((lane & 3) << 1) + ((u >> 1) << 3);
    unsigned h0 = __half_as_ushort(
        __float2half_rn(w[((size_t)co * 256 + ci0) * 9 + tap]));
    unsigned h1 = __half_as_ushort(
        __float2half_rn(w[((size_t)co * 256 + ci0 + 1) * 9 + tap]));
    g_wf[idx] = (h1 << 16) | h0;
}

// ---------------- Kernel 4: fp16 mma conv ----------------
// smem (double-buffered): per buffer:
//   xs[row(6)][slot(66)][96B]                 (38016 B)
//   ws[tap(9)][k16(2)][ct8(8)][512B]          (73728 B)
#define XS_SLOT 96
#define XS_M (66 * XS_SLOT)        // 6336
#define XS_TOT (6 * XS_M)          // 38016
#define WS_TOT 73728
#define BUF_SZ (XS_TOT + WS_TOT)   // 111744
#define SMEM_TOTAL (2 * BUF_SZ)    // 223488

__global__ __launch_bounds__(512, 1)
void conv_mma_kernel(const float* __restrict__ bias, float* __restrict__ out) {
    extern __shared__ __align__(16) char smem[];
    const uint32_t sb = smem_u32(smem);
    const int tid = threadIdx.x;
    const int wid = tid >> 5;
    const int lane = tid & 31;

    const int strip = blockIdx.x;          // 0..15 -> 4 rows each
    const int half  = blockIdx.y;          // 0..1
    const int b     = blockIdx.z;          // 0..15
    const int y0    = strip << 2;

    const int wm = wid >> 2;               // 0..3 (co 32-tile)
    const int wn = wid & 3;                // 0..3 (output row)
    const int ln4 = lane & 3, lq = lane >> 2;

    // ---- staging helper (cp.async, one group per chunk) ----
    auto stage = [&](int chunk, uint32_t bufbase) {
        const int k16b = chunk * 2;
        // weights: 9 taps x 2 k16 x 8 ct8 x 32 lanes = 4608 uint4
#pragma unroll
        for (int it = 0; it < 9; ++it) {
            int idx = tid + it * 512;
            int tap = idx >> 9, rem = idx & 511;
            int k16i = rem >> 8, ct8 = (rem >> 5) & 7, ln = rem & 31;
            const uint4* g = (const uint4*)g_wf +
                ((((size_t)tap * 16 + k16b + k16i) * 16 + half * 8 + ct8) << 5) + ln;
            uint32_t d = bufbase + XS_TOT + tap * 8192 + k16i * 4096 +
                         ct8 * 512 + ln * 16;
            CP16(d, g, 16);
        }
        // input: 6 rows x 64 px x 4 quads = 1536 uint4 (OOB rows zero-fill)
#pragma unroll
        for (int it = 0; it < 3; ++it) {
            int idx = tid + it * 512;
            int m = idx >> 8, rem = idx & 255;
            int px = rem >> 2, qq = rem & 3;
            int yi = y0 + m - 1;
            const __half* g = g_pt +
                ((((size_t)b * 64 + (yi & 63)) * 64 + px) << 8) +
                chunk * 32 + qq * 8;
            int sz = ((unsigned)yi < 64u) ? 16 : 0;
            CP16(bufbase + m * XS_M + (px + 1) * XS_SLOT + qq * 16, g, sz);
        }
        CP_COMMIT();
    };

    // prefetch chunk 0 into buffer 0
    stage(0, sb);

    // permanent zero borders (slots 0 and 65), both buffers
    if (tid < 96) {
        int bf = tid / 48, rem = tid % 48;
        int m = rem / 8, r2 = rem % 8;
        int s = r2 / 4, qq = r2 % 4;
        *(uint4*)(smem + bf * BUF_SZ + m * XS_M + (s ? 65 : 0) * XS_SLOT +
                  qq * 16) = make_uint4(0, 0, 0, 0);
    }

    float acc[2][8][4];
#pragma unroll
    for (int i = 0; i < 2; ++i)
#pragma unroll
        for (int jj = 0; jj < 8; ++jj)
#pragma unroll
            for (int k = 0; k < 4; ++k) acc[i][jj][k] = 0.0f;

#pragma unroll 1
    for (int chunk = 0; chunk < 8; ++chunk) {
        CP_WAIT0();
        __syncthreads();
        if (chunk < 7) stage(chunk + 1, sb + ((chunk + 1) & 1) * BUF_SZ);

        const uint32_t xb = sb + (chunk & 1) * BUF_SZ;
        const uint32_t wb = xb + XS_TOT;

#pragma unroll
        for (int tap = 0; tap < 9; ++tap) {
            const int dy = tap / 3, dx = tap - dy * 3;
            const uint32_t bb = xb + (wn + dy) * XS_M +
                                (lq + dx) * XS_SLOT + ln4 * 8;
            const uint32_t ab = wb + tap * 8192 + wm * 1024 + lane * 16;
#pragma unroll
            for (int ks = 0; ks < 2; ++ks) {
                uint32_t a0[4], a1[4];
                LDS128U(a0, ab + ks * 4096);
                LDS128U(a1, ab + ks * 4096 + 512);
#pragma unroll
                for (int nb = 0; nb < 8; ++nb) {
                    uint32_t bfr[2];
                    LDS64U(bfr, bb + nb * (8 * XS_SLOT) + ks * 32);
                    MMA_F16(acc[0][nb], a0, bfr);
                    MMA_F16(acc[1][nb], a1, bfr);
                }
            }
        }
    }

    // ---- epilogue ----
#pragma unroll
    for (int mf = 0; mf < 2; ++mf) {
        int co = half * 128 + wm * 32 + mf * 16 + lq;
        float bv0 = bias[co];
        float bv1 = bias[co + 8];
        float* o0 = out + (((size_t)b * 256 + co) << 12) + ((y0 + wn) << 6);
        float* o1 = o0 + (8 << 12);
#pragma unroll
        for (int nb = 0; nb < 8; ++nb) {
            int xp = nb * 8 + ln4 * 2;
            *(float2*)(o0 + xp) =
                make_float2(acc[mf][nb][0] + bv0, acc[mf][nb][1] + bv0);
            *(float2*)(o1 + xp) =
                make_float2(acc[mf][nb][2] + bv1, acc[mf][nb][3] + bv1);
        }
    }
}

// ---------------- launch ----------------
extern "C" void kernel_launch(void* const* d_in, const int* in_sizes, int n_in,
                              void* d_out, int out_size) {
    const float* x    = (const float*)d_in[0];
    const float* w    = (const float*)d_in[1];
    const float* bias = (const float*)d_in[2];
    float* out = (float*)d_out;

    static int smem_set = 0;
    if (!smem_set) {
        cudaFuncSetAttribute(conv_mma_kernel,
                             cudaFuncAttributeMaxDynamicSharedMemorySize,
                             SMEM_TOTAL);
        smem_set = 1;
    }

    energy_argmax_kernel<<<512, 256>>>(x);     // launch 0
    pool_kernel<<<1024, 256>>>(x);             // launch 1
    wprep_kernel<<<1152, 256>>>(w);            // launch 2

    dim3 grid(16, 2, 16);                      // strips, co halves, batch
    conv_mma_kernel<<<grid, 512, SMEM_TOTAL>>>(bias, out);   // launch 3
}

// round 12
// speedup vs baseline: 14.0587x; 1.0001x over previous
#include <cuda_runtime.h>
#include <cuda_fp16.h>
#include <cstdint>

// ---------------------------------------------------------------------------
// G2Conv2d4, fp16 mma.sync m16n8k16 (Round 11: 64x64 warp tiles).
//   argmax -> pooled = in-rect ? max(x^2, landmark) : x^2  (one-hot collapse)
//   conv3x3 = 9 shifted GEMMs, fp16 inputs, fp32 accumulate.
// CTA: 128 co x 4 rows x 64 px, 256 threads (8 warps, 2m x 4n).
// Warp tile 64co x 64px (acc = 128 fp32 regs) -> 128 B/MMA crossbar traffic
// (was 192). Input slots repacked so one LDS.128/thread yields the B frags of
// BOTH k16 groups; slot stride 64B is phase-conflict-free. All 9 taps'
// weights + input tile cp.async double-buffered; one barrier per ci-chunk.
// ---------------------------------------------------------------------------

__device__ unsigned long long g_part[512];                    // argmax partials
__device__ __align__(16) __half g_pt[16ull * 64 * 64 * 256];  // pooled 33.5MB
__device__ __align__(16) uint32_t g_wf[9 * 16 * 16 * 32 * 4]; // frag-major w

__device__ __forceinline__ uint32_t smem_u32(const void* p) {
    uint32_t a;
    asm("{ .reg .u64 t; cvta.to.shared.u64 t, %1; cvt.u32.u64 %0, t; }"
        : "=r"(a) : "l"(p));
    return a;
}

#define LDS128U(r, addr)                                                      \
    asm volatile("ld.shared.v4.b32 {%0,%1,%2,%3}, [%4];"                      \
                 : "=r"((r)[0]), "=r"((r)[1]), "=r"((r)[2]), "=r"((r)[3])     \
                 : "r"(addr))
#define MMA_F16(d, a, b0, b1)                                                 \
    asm volatile(                                                             \
        "mma.sync.aligned.m16n8k16.row.col.f32.f16.f16.f32 "                  \
        "{%0,%1,%2,%3}, {%4,%5,%6,%7}, {%8,%9}, {%0,%1,%2,%3};"               \
        : "+f"((d)[0]), "+f"((d)[1]), "+f"((d)[2]), "+f"((d)[3])              \
        : "r"((a)[0]), "r"((a)[1]), "r"((a)[2]), "r"((a)[3]),                 \
          "r"(b0), "r"(b1))
#define CP16(dst, src, sz)                                                    \
    asm volatile("cp.async.cg.shared.global [%0], [%1], 16, %2;"              \
                 :: "r"(dst), "l"(src), "r"(sz))
#define CP_COMMIT() asm volatile("cp.async.commit_group;" ::: "memory")
#define CP_WAIT0()  asm volatile("cp.async.wait_group 0;" ::: "memory")

// ---------------- Kernel 1: energy argmax partials ----------------
__global__ void energy_argmax_kernel(const float* __restrict__ x) {
    int bq    = blockIdx.x >> 3;
    int slice = blockIdx.x & 7;
    int b = bq >> 2, q = bq & 3;
    const float* xb = x + (((size_t)b * 256 + q * 64) << 12);

    unsigned long long best = 0ull;
    int p0 = slice * 512;
    for (int p = p0 + threadIdx.x; p < p0 + 512; p += 256) {
        float s = 0.0f;
#pragma unroll 8
        for (int c = 0; c < 64; ++c) {
            float v = xb[((size_t)c << 12) + p];
            s = fmaf(v, v, s);
        }
        unsigned long long key =
            ((unsigned long long)__float_as_uint(s) << 32) |
            (unsigned long long)(unsigned)(~p);
        if (key > best) best = key;
    }
    __shared__ unsigned long long sk[256];
    sk[threadIdx.x] = best;
    __syncthreads();
    for (int off = 128; off; off >>= 1) {
        if (threadIdx.x < off) {
            unsigned long long o = sk[threadIdx.x + off];
            if (o > sk[threadIdx.x]) sk[threadIdx.x] = o;
        }
        __syncthreads();
    }
    if (threadIdx.x == 0) g_part[blockIdx.x] = sk[0];
}

// ---------------- Kernel 2: pooled x^2 -> fp16, packed-B interleave ------
// layout: [pixel*256 + ci'], ci' within each 32-group packs, per thread t,
// 16B = {k16g0:{2t,2t+1,2t+8,2t+9}, k16g1: same}:
//   pos(j) = 8*((j&7)>>1) + 4*(j>>4) + 2*((j&15)>>3) + (j&1)
__global__ void pool_kernel(const float* __restrict__ x) {
    int bid = blockIdx.x;              // b*64 + y
    int b = bid >> 6, y = bid & 63;
    int ci = threadIdx.x;
    int q = ci >> 6;
    int bq = (b << 2) | q;

    unsigned long long key = 0ull;
#pragma unroll
    for (int s = 0; s < 8; ++s) {
        unsigned long long o = g_part[bq * 8 + s];
        if (o > key) key = o;
    }
    int p = (int)(~(unsigned)key) & 4095;
    int r = p >> 6, c = p & 63;

    const float* xc = x + ((size_t)(b * 256 + ci) << 12);
    float lv = xc[(r << 6) | c];
    lv *= lv;
    bool ch = (q < 2) ? (y <= r) : (y >= r);
    bool leftW = ((q & 1) == 0);

    int j = ci & 31;
    int pos = 8 * ((j & 7) >> 1) + 4 * (j >> 4) + 2 * ((j & 15) >> 3) + (j & 1);
    int ci_perm = (ci & ~31) + pos;

    const float4* row4 = (const float4*)(xc + (y << 6));
    size_t obase = (((size_t)bid << 6) << 8) + ci_perm;

#pragma unroll 4
    for (int i = 0; i < 16; ++i) {
        float4 v = row4[i];
        int x0 = i << 2;
        float s[4] = {v.x * v.x, v.y * v.y, v.z * v.z, v.w * v.w};
        if (ch) {
#pragma unroll
            for (int jj = 0; jj < 4; ++jj)
                if (leftW ? (x0 + jj <= c) : (x0 + jj >= c))
                    s[jj] = fmaxf(s[jj], lv);
        }
#pragma unroll
        for (int jj = 0; jj < 4; ++jj)
            g_pt[obase + ((size_t)(x0 + jj) << 8)] = __float2half_rn(s[jj]);
    }
}

// ---------------- Kernel 3: weights -> fragment-major fp16 --------------
// g_wf u32 idx: (((tap*16 + k16)*16 + ct)*32 + lane)*4 + u
//   co = ct*16 + (lane>>2) + 8*(u&1);  ci = k16*16 + 2*(lane&3) + 8*(u>>1) + p
__global__ void wprep_kernel(const float* __restrict__ w) {
    int idx = blockIdx.x * 256 + threadIdx.x;     // 1152 blocks = 294912
    int u    = idx & 3;
    int lane = (idx >> 2) & 31;
    int ct   = (idx >> 7) & 15;
    int k16  = (idx >> 11) & 15;
    int tap  = idx >> 15;
    int co  = ct * 16 + (lane >> 2) + ((u & 1) << 3);
    int ci0 = k16 * 16 + ((lane & 3) << 1) + ((u >> 1) << 3);
    unsigned h0 = __half_as_ushort(
        __float2half_rn(w[((size_t)co * 256 + ci0) * 9 + tap]));
    unsigned h1 = __half_as_ushort(
        __float2half_rn(w[((size_t)co * 256 + ci0 + 1) * 9 + tap]));
    g_wf[idx] = (h1 << 16) | h0;
}

// ---------------- Kernel 4: fp16 mma conv ----------------
// smem per buffer: xs[row(6)][slot(66)][64B]  (25344 B)
//                  ws[tap(9)][k16(2)][ct8(8)][512B]  (73728 B)
#define XS_SLOT 64
#define XS_M (66 * XS_SLOT)        // 4224
#define XS_TOT (6 * XS_M)          // 25344
#define WS_TOT 73728
#define BUF_SZ (XS_TOT + WS_TOT)   // 99072
#define SMEM_TOTAL (2 * BUF_SZ)    // 198144

__global__ __launch_bounds__(256, 1)
void conv_mma_kernel(const float* __restrict__ bias, float* __restrict__ out) {
    extern __shared__ __align__(16) char smem[];
    const uint32_t sb = smem_u32(smem);
    const int tid = threadIdx.x;
    const int wid = tid >> 5;
    const int lane = tid & 31;

    const int strip = blockIdx.x;          // 0..15 -> 4 rows each
    const int half  = blockIdx.y;          // 0..1
    const int b     = blockIdx.z;          // 0..15
    const int y0    = strip << 2;

    const int wm = wid >> 2;               // 0..1 (co 64-tile)
    const int wn = wid & 3;                // 0..3 (output row)
    const int ln4 = lane & 3, lq = lane >> 2;

    // ---- staging helper (cp.async, one group per chunk) ----
    auto stage = [&](int chunk, uint32_t bufbase) {
        const int k16b = chunk * 2;
        // weights: 9 taps x 2 k16 x 8 ct8 x 32 lanes = 4608 uint4
#pragma unroll
        for (int it = 0; it < 18; ++it) {
            int idx = tid + it * 256;
            int tap = idx >> 9, rem = idx & 511;
            int k16i = rem >> 8, ct8 = (rem >> 5) & 7, ln = rem & 31;
            const uint4* g = (const uint4*)g_wf +
                ((((size_t)tap * 16 + k16b + k16i) * 16 + half * 8 + ct8) << 5) + ln;
            uint32_t d = bufbase + XS_TOT + tap * 8192 + k16i * 4096 +
                         ct8 * 512 + ln * 16;
            CP16(d, g, 16);
        }
        // input: 6 rows x 64 px x 4 quads = 1536 uint4 (OOB rows zero-fill)
#pragma unroll
        for (int it = 0; it < 6; ++it) {
            int idx = tid + it * 256;
            int m = idx >> 8, rem = idx & 255;
            int px = rem >> 2, qq = rem & 3;
            int yi = y0 + m - 1;
            const __half* g = g_pt +
                ((((size_t)b * 64 + (yi & 63)) * 64 + px) << 8) +
                chunk * 32 + qq * 8;
            int sz = ((unsigned)yi < 64u) ? 16 : 0;
            CP16(bufbase + m * XS_M + (px + 1) * XS_SLOT + qq * 16, g, sz);
        }
        CP_COMMIT();
    };

    // prefetch chunk 0 into buffer 0
    stage(0, sb);

    // permanent zero borders (slots 0 and 65), both buffers: 96 uint4
    if (tid < 96) {
        int bf = tid / 48, rem = tid % 48;
        int m = rem / 8, r2 = rem % 8;
        int s = r2 / 4, qq = r2 % 4;
        *(uint4*)(smem + bf * BUF_SZ + m * XS_M + (s ? 65 : 0) * XS_SLOT +
                  qq * 16) = make_uint4(0, 0, 0, 0);
    }

    float acc[4][8][4];
#pragma unroll
    for (int i = 0; i < 4; ++i)
#pragma unroll
        for (int jj = 0; jj < 8; ++jj)
#pragma unroll
            for (int k = 0; k < 4; ++k) acc[i][jj][k] = 0.0f;

#pragma unroll 1
    for (int chunk = 0; chunk < 8; ++chunk) {
        CP_WAIT0();
        __syncthreads();
        if (chunk < 7) stage(chunk + 1, sb + ((chunk + 1) & 1) * BUF_SZ);

        const uint32_t xb = sb + (chunk & 1) * BUF_SZ;
        const uint32_t wb = xb + XS_TOT;

#pragma unroll
        for (int tap = 0; tap < 9; ++tap) {
            const int dy = tap / 3, dx = tap - dy * 3;
            const uint32_t bb = xb + (wn + dy) * XS_M +
                                (lq + dx) * XS_SLOT + ln4 * 16;
            const uint32_t ab = wb + tap * 8192 + (wm * 4) * 512 + lane * 16;

            // preload A frags for both k16 groups (8x LDS.128 = 32 regs)
            uint32_t a[2][4][4];
#pragma unroll
            for (int ks = 0; ks < 2; ++ks)
#pragma unroll
                for (int mi = 0; mi < 4; ++mi)
                    LDS128U(a[ks][mi], ab + ks * 4096 + mi * 512);

#pragma unroll
            for (int nb = 0; nb < 8; ++nb) {
                uint32_t bq4[4];                 // both ks frags in one LDS.128
                LDS128U(bq4, bb + nb * (8 * XS_SLOT));
#pragma unroll
                for (int mi = 0; mi < 4; ++mi) {
                    MMA_F16(acc[mi][nb], a[0][mi], bq4[0], bq4[1]);
                    MMA_F16(acc[mi][nb], a[1][mi], bq4[2], bq4[3]);
                }
            }
        }
    }

    // ---- epilogue ----
#pragma unroll
    for (int mi = 0; mi < 4; ++mi) {
        int co = half * 128 + wm * 64 + mi * 16 + lq;
        float bv0 = bias[co];
        float bv1 = bias[co + 8];
        float* o0 = out + (((size_t)b * 256 + co) << 12) + ((y0 + wn) << 6);
        float* o1 = o0 + (8 << 12);
#pragma unroll
        for (int nb = 0; nb < 8; ++nb) {
            int xp = nb * 8 + ln4 * 2;
            *(float2*)(o0 + xp) =
                make_float2(acc[mi][nb][0] + bv0, acc[mi][nb][1] + bv0);
            *(float2*)(o1 + xp) =
                make_float2(acc[mi][nb][2] + bv1, acc[mi][nb][3] + bv1);
        }
    }
}

// ---------------- launch ----------------
extern "C" void kernel_launch(void* const* d_in, const int* in_sizes, int n_in,
                              void* d_out, int out_size) {
    const float* x    = (const float*)d_in[0];
    const float* w    = (const float*)d_in[1];
    const float* bias = (const float*)d_in[2];
    float* out = (float*)d_out;

    static int smem_set = 0;
    if (!smem_set) {
        cudaFuncSetAttribute(conv_mma_kernel,
                             cudaFuncAttributeMaxDynamicSharedMemorySize,
                             SMEM_TOTAL);
        smem_set = 1;
    }

    energy_argmax_kernel<<<512, 256>>>(x);     // launch 0
    pool_kernel<<<1024, 256>>>(x);             // launch 1
    wprep_kernel<<<1152, 256>>>(w);            // launch 2

    dim3 grid(16, 2, 16);                      // strips, co halves, batch
    conv_mma_kernel<<<grid, 256, SMEM_TOTAL>>>(bias, out);   // launch 3
}